// round 1
// baseline (speedup 1.0000x reference)
#include <cuda_runtime.h>
#include <math.h>

#define NHALF 4096
#define NROWS 8192
#define D 256

#define BM 128
#define BN 128
#define BK 32
#define CSPLIT 8
#define CTILES (NROWS / BN / CSPLIT)   // 8 column tiles per block

// Device-global scratch (no allocations allowed in kernel_launch)
__device__ float g_zn[NROWS * D];      // normalized rows, 8 MB
__device__ float g_denom[NROWS];       // per-row sum of masked exp(2*sim)
__device__ float g_pos[NHALF];         // positive-pair similarities
__device__ float g_acc[2];             // weighted loss numerator / weight sum

// ---------------------------------------------------------------------------
// K1: normalize each row of concat(z_i, z_j); also zero the accumulators.
// One block (256 threads) per row; D == 256 so one element per thread.
// ---------------------------------------------------------------------------
__global__ void k_normalize(const float* __restrict__ z_i,
                            const float* __restrict__ z_j) {
    int row = blockIdx.x;
    int t = threadIdx.x;
    const float* src = (row < NHALF) ? (z_i + (size_t)row * D)
                                     : (z_j + (size_t)(row - NHALF) * D);
    float v = src[t];
    float ss = v * v;
#pragma unroll
    for (int o = 16; o; o >>= 1) ss += __shfl_xor_sync(0xffffffffu, ss, o);
    __shared__ float sh[8];
    if ((t & 31) == 0) sh[t >> 5] = ss;
    __syncthreads();
    float tot = 0.f;
#pragma unroll
    for (int i = 0; i < 8; i++) tot += sh[i];
    float norm = fmaxf(sqrtf(tot), 1e-8f);   // reference clamps norm at EPS
    g_zn[(size_t)row * D + t] = v / norm;
    if (t == 0) {
        g_denom[row] = 0.f;
        if (row == 0) { g_acc[0] = 0.f; g_acc[1] = 0.f; }
    }
}

// ---------------------------------------------------------------------------
// K2: fused sim GEMM + exp + masked row-sum.
// Grid (NROWS/BM, CSPLIT); each block: 128 rows x (NROWS/CSPLIT) cols.
// 256 threads as 16x16, each owning an 8x8 fp32 accumulator tile.
// ---------------------------------------------------------------------------
__global__ void __launch_bounds__(256) k_sim() {
    __shared__ float As[BM][BK + 1];   // +1 pad: conflict-free scalar stores,
                                       // 2-address broadcast a-reads
    __shared__ float Bs[BK][BN];       // k-major: float4 b-reads

    const int tid = threadIdx.x;
    const int tx = tid & 15;
    const int ty = tid >> 4;
    const int row0 = blockIdx.x * BM;
    const int lk4 = tid & 7;           // float4 index along K for loads
    const int lm = tid >> 3;           // 0..31 row-within-pass for loads

    float rsum[8];
#pragma unroll
    for (int i = 0; i < 8; i++) rsum[i] = 0.f;

    for (int ct = 0; ct < CTILES; ct++) {
        const int col0 = (blockIdx.y * CTILES + ct) * BN;

        float acc[8][8];
#pragma unroll
        for (int i = 0; i < 8; i++)
#pragma unroll
            for (int j = 0; j < 8; j++) acc[i][j] = 0.f;

        for (int k0 = 0; k0 < D; k0 += BK) {
            // Load A tile (rows row0..+127, k k0..+31), row-major in smem.
#pragma unroll
            for (int p = 0; p < 4; p++) {
                int m = lm + p * 32;
                float4 v = *(const float4*)&g_zn[(size_t)(row0 + m) * D + k0 + lk4 * 4];
                As[m][lk4 * 4 + 0] = v.x;
                As[m][lk4 * 4 + 1] = v.y;
                As[m][lk4 * 4 + 2] = v.z;
                As[m][lk4 * 4 + 3] = v.w;
            }
            // Load B tile transposed to k-major for vectorized n-reads.
#pragma unroll
            for (int p = 0; p < 4; p++) {
                int n = lm + p * 32;
                float4 v = *(const float4*)&g_zn[(size_t)(col0 + n) * D + k0 + lk4 * 4];
                Bs[lk4 * 4 + 0][n] = v.x;
                Bs[lk4 * 4 + 1][n] = v.y;
                Bs[lk4 * 4 + 2][n] = v.z;
                Bs[lk4 * 4 + 3][n] = v.w;
            }
            __syncthreads();

#pragma unroll
            for (int k = 0; k < BK; k++) {
                float a[8], b[8];
#pragma unroll
                for (int i = 0; i < 8; i++) a[i] = As[ty * 8 + i][k];
                float4 b0 = *(const float4*)&Bs[k][tx * 8];
                float4 b1 = *(const float4*)&Bs[k][tx * 8 + 4];
                b[0] = b0.x; b[1] = b0.y; b[2] = b0.z; b[3] = b0.w;
                b[4] = b1.x; b[5] = b1.y; b[6] = b1.z; b[7] = b1.w;
#pragma unroll
                for (int i = 0; i < 8; i++)
#pragma unroll
                    for (int j = 0; j < 8; j++)
                        acc[i][j] = fmaf(a[i], b[j], acc[i][j]);
            }
            __syncthreads();
        }

        // Epilogue: exp(sim/T) with T=0.5, mask only the true diagonal.
        if (row0 != col0) {
#pragma unroll
            for (int i = 0; i < 8; i++)
#pragma unroll
                for (int j = 0; j < 8; j++)
                    rsum[i] += __expf(2.0f * acc[i][j]);
        } else {
            int gr = ty * 8;
            int gc = tx * 8;
#pragma unroll
            for (int i = 0; i < 8; i++)
#pragma unroll
                for (int j = 0; j < 8; j++)
                    if (gr + i != gc + j) rsum[i] += __expf(2.0f * acc[i][j]);
        }
    }

    // Reduce rsum across the 16 threads sharing each row (tx group = half warp),
    // then one atomicAdd per row.
#pragma unroll
    for (int i = 0; i < 8; i++) {
        float v = rsum[i];
#pragma unroll
        for (int o = 8; o; o >>= 1) v += __shfl_xor_sync(0xffffffffu, v, o);
        if (tx == 0) atomicAdd(&g_denom[row0 + ty * 8 + i], v);
    }
}

// ---------------------------------------------------------------------------
// K3: positive-pair similarities p_i = dot(zn[i], zn[i+N]). One warp per i.
// ---------------------------------------------------------------------------
__global__ void k_pos() {
    int gw = (blockIdx.x * blockDim.x + threadIdx.x) >> 5;   // 0..4095
    int lane = threadIdx.x & 31;
    const float4* a = (const float4*)(g_zn + (size_t)gw * D);
    const float4* b = (const float4*)(g_zn + (size_t)(gw + NHALF) * D);
    float s = 0.f;
#pragma unroll
    for (int p = 0; p < 2; p++) {
        float4 x = a[lane + p * 32];
        float4 y = b[lane + p * 32];
        s += x.x * y.x + x.y * y.y + x.z * y.z + x.w * y.w;
    }
#pragma unroll
    for (int o = 16; o; o >>= 1) s += __shfl_xor_sync(0xffffffffu, s, o);
    if (lane == 0) g_pos[gw] = s;
}

// ---------------------------------------------------------------------------
// K4: weighted loss reduction.
// loss_r = log(denom_r) - 2*pos_r ; sum w2[r]*loss_r, w2 = tile(weights,2).
// Pairs (i, i+N) share pos and weight: contribution
//   w_i * (log(den_i) + log(den_{i+N}) - 4*p_i), weight-sum 2*w_i.
// ---------------------------------------------------------------------------
__global__ void k_loss(const float* __restrict__ w) {
    int i = blockIdx.x * blockDim.x + threadIdx.x;   // 4096 threads total
    float wi = w[i];
    float num = wi * (logf(g_denom[i]) + logf(g_denom[i + NHALF]) - 4.0f * g_pos[i]);
    float den = 2.0f * wi;
#pragma unroll
    for (int o = 16; o; o >>= 1) {
        num += __shfl_xor_sync(0xffffffffu, num, o);
        den += __shfl_xor_sync(0xffffffffu, den, o);
    }
    __shared__ float s_num[8], s_den[8];
    int lane = threadIdx.x & 31, wrp = threadIdx.x >> 5;
    if (lane == 0) { s_num[wrp] = num; s_den[wrp] = den; }
    __syncthreads();
    if (threadIdx.x == 0) {
        float n = 0.f, d = 0.f;
#pragma unroll
        for (int j = 0; j < 8; j++) { n += s_num[j]; d += s_den[j]; }
        atomicAdd(&g_acc[0], n);
        atomicAdd(&g_acc[1], d);
    }
}

__global__ void k_final(float* __restrict__ out) {
    out[0] = g_acc[0] / g_acc[1];
}

// ---------------------------------------------------------------------------
extern "C" void kernel_launch(void* const* d_in, const int* in_sizes, int n_in,
                              void* d_out, int out_size) {
    const float* z_i = (const float*)d_in[0];
    const float* z_j = (const float*)d_in[1];
    const float* w   = (const float*)d_in[2];
    float* out = (float*)d_out;

    k_normalize<<<NROWS, 256>>>(z_i, z_j);
    k_sim<<<dim3(NROWS / BM, CSPLIT), 256>>>();
    k_pos<<<NHALF * 32 / 256, 256>>>();
    k_loss<<<NHALF / 256, 256>>>(w);
    k_final<<<1, 1>>>(out);
}

// round 3
// speedup vs baseline: 7.6182x; 7.6182x over previous
#include <cuda_runtime.h>
#include <cuda_bf16.h>
#include <cstdint>
#include <math.h>

#define NHALF 4096
#define NROWS 8192
#define D 256

#define BM 128
#define BN 128
#define CSPLIT 2
#define NT (NROWS / CSPLIT / BN)     // 32 col tiles per CTA

// ---------------- device globals (no allocs allowed) ----------------
__device__ __align__(16) float         g_zn[NROWS * D];    // fp32 rows (pos kernel)
__device__ __align__(16) __nv_bfloat16 g_zbf[NROWS * D];   // bf16 rows (MMA)
__device__ float g_denom[NROWS];
__device__ float g_pos[NHALF];
__device__ float g_acc[2];

// ---------------- PTX helpers (arch-portable: sm_80+ forms only) ----------
__device__ __forceinline__ uint32_t smem_u32(const void* p) {
    uint32_t a;
    asm("{ .reg .u64 t; cvta.to.shared.u64 t, %1; cvt.u32.u64 %0, t; }" : "=r"(a) : "l"(p));
    return a;
}
#define CPASYNC16(dst, src) \
    asm volatile("cp.async.cg.shared.global [%0], [%1], 16;" :: "r"(dst), "l"(src))
#define CPCOMMIT() asm volatile("cp.async.commit_group;" ::: "memory")
#define CPWAIT(n)  asm volatile("cp.async.wait_group %0;" :: "n"(n) : "memory")

#define LDSM4(r0, r1, r2, r3, a) \
    asm volatile("ldmatrix.sync.aligned.m8n8.x4.shared.b16 {%0,%1,%2,%3},[%4];" \
        : "=r"(r0), "=r"(r1), "=r"(r2), "=r"(r3) : "r"(a))

#define MMA16816(d, a, b) \
    asm volatile("mma.sync.aligned.m16n8k16.row.col.f32.bf16.bf16.f32 " \
        "{%0,%1,%2,%3},{%4,%5,%6,%7},{%8,%9},{%0,%1,%2,%3};" \
        : "+f"((d)[0]), "+f"((d)[1]), "+f"((d)[2]), "+f"((d)[3]) \
        : "r"((a)[0]), "r"((a)[1]), "r"((a)[2]), "r"((a)[3]), "r"((b)[0]), "r"((b)[1]))

// fast 2^t on fma/alu pipes (|t| <= 3.2 here), no MUFU
__device__ __forceinline__ float fexp2(float t) {
    float r = t + 12582912.0f;
    int   n = __float_as_int(r) - 0x4B400000;
    float f = t - (r - 12582912.0f);
    float p = 1.3333558e-3f;
    p = fmaf(p, f, 9.6181291e-3f);
    p = fmaf(p, f, 5.5504109e-2f);
    p = fmaf(p, f, 2.4022651e-1f);
    p = fmaf(p, f, 6.9314718e-1f);
    p = fmaf(p, f, 1.0f);
    return __int_as_float(__float_as_int(p) + (n << 23));
}

// ---------------------------------------------------------------------------
// K1: normalize rows of concat(z_i,z_j): fp32 + bf16 copies; zero accumulators.
// ---------------------------------------------------------------------------
__global__ void k_normalize(const float* __restrict__ z_i,
                            const float* __restrict__ z_j) {
    int row = blockIdx.x;
    int t = threadIdx.x;
    const float* src = (row < NHALF) ? (z_i + (size_t)row * D)
                                     : (z_j + (size_t)(row - NHALF) * D);
    float v = src[t];
    float ss = v * v;
#pragma unroll
    for (int o = 16; o; o >>= 1) ss += __shfl_xor_sync(0xffffffffu, ss, o);
    __shared__ float sh[8];
    if ((t & 31) == 0) sh[t >> 5] = ss;
    __syncthreads();
    float tot = 0.f;
#pragma unroll
    for (int i = 0; i < 8; i++) tot += sh[i];
    float norm = fmaxf(sqrtf(tot), 1e-8f);
    float zn = v / norm;
    g_zn[(size_t)row * D + t] = zn;
    g_zbf[(size_t)row * D + t] = __float2bfloat16(zn);
    if (t == 0) {
        g_denom[row] = 0.f;
        if (row == 0) { g_acc[0] = 0.f; g_acc[1] = 0.f; }
    }
}

// ---------------------------------------------------------------------------
// Async-copy one 128x256 bf16 tile into XOR-swizzled SMEM.
// SMEM row = 512B = 32 x 16B chunks; chunk cc stored at cc ^ (row & 7).
// ---------------------------------------------------------------------------
__device__ __forceinline__ void load_tile_async(uint32_t sdst, const char* gsrc, int tid) {
#pragma unroll
    for (int i = 0; i < 16; i++) {
        int c = tid + i * 256;            // 0..4095
        int r = c >> 5, cc = c & 31;
        uint32_t dst = sdst + r * 512 + ((cc ^ (r & 7)) << 4);
        CPASYNC16(dst, gsrc + (size_t)c * 16);
    }
}

// ---------------------------------------------------------------------------
// K2: HMMA sim GEMM + poly-exp + masked row-sum.
// Grid (64, CSPLIT), 256 threads = 8 warps (4 row x 2 col), warp tile 32x64.
// ---------------------------------------------------------------------------
__global__ void __launch_bounds__(256) k_sim() {
    extern __shared__ char smem[];
    const int tid = threadIdx.x;
    const int wid = tid >> 5, lane = tid & 31;
    const int row0 = blockIdx.x * BM;
    const int colbase = blockIdx.y * (NROWS / CSPLIT);
    const int warp_row = (wid & 3) * 32;
    const int warp_col = (wid >> 2) * 64;

    const uint32_t sbA = smem_u32(smem);
    const uint32_t sbB[2] = { sbA + 65536, sbA + 131072 };

    // prologue: A tile + B tile 0 in flight as one group
    load_tile_async(sbA, (const char*)(g_zbf + (size_t)row0 * D), tid);
    load_tile_async(sbB[0], (const char*)(g_zbf + (size_t)colbase * D), tid);
    CPCOMMIT();

    // ldmatrix address precompute
    // A (x4): lanes0-7 rows m0-7 klo | 8-15 rows m8-15 klo | 16-23 m0-7 khi | 24-31 m8-15 khi
    uint32_t baseA[2]; int swA[2];
    const int hiA = lane >> 4;
#pragma unroll
    for (int mi = 0; mi < 2; mi++) {
        int rA = warp_row + mi * 16 + (lane & 15);
        baseA[mi] = sbA + rA * 512;
        swA[mi] = rA & 7;
    }
    // B (x4): lanes0-7 n0-7 klo | 8-15 n0-7 khi | 16-23 n8-15 klo | 24-31 n8-15 khi
    uint32_t relB[4]; int swB[4];
    const int hiB = (lane >> 3) & 1;
#pragma unroll
    for (int np = 0; np < 4; np++) {
        int nB = warp_col + np * 16 + (lane & 7) + ((lane & 16) >> 1);
        relB[np] = nB * 512;
        swB[np] = nB & 7;
    }

    float rsum[2][2] = {{0.f, 0.f}, {0.f, 0.f}};
    const float K2E = 2.8853900817779268f;   // 2 / ln(2)

    for (int ct = 0; ct < NT; ct++) {
        const uint32_t sbBt = sbB[ct & 1];
        if (ct + 1 < NT) {
            load_tile_async(sbB[(ct + 1) & 1],
                            (const char*)(g_zbf + (size_t)(colbase + (ct + 1) * BN) * D), tid);
            CPCOMMIT();
            CPWAIT(1);
        } else {
            CPWAIT(0);
        }
        __syncthreads();

        float acc[2][8][4];
#pragma unroll
        for (int mi = 0; mi < 2; mi++)
#pragma unroll
            for (int ni = 0; ni < 8; ni++)
#pragma unroll
                for (int c = 0; c < 4; c++) acc[mi][ni][c] = 0.f;

#pragma unroll
        for (int s = 0; s < 16; s++) {
            uint32_t af[2][4];
#pragma unroll
            for (int mi = 0; mi < 2; mi++)
                LDSM4(af[mi][0], af[mi][1], af[mi][2], af[mi][3],
                      baseA[mi] + (((2 * s + hiA) ^ swA[mi]) << 4));
            uint32_t bf[8][2];
#pragma unroll
            for (int np = 0; np < 4; np++) {
                uint32_t t0, t1, t2, t3;
                LDSM4(t0, t1, t2, t3,
                      sbBt + relB[np] + (((2 * s + hiB) ^ swB[np]) << 4));
                bf[2 * np][0] = t0;     bf[2 * np][1] = t1;
                bf[2 * np + 1][0] = t2; bf[2 * np + 1][1] = t3;
            }
#pragma unroll
            for (int mi = 0; mi < 2; mi++)
#pragma unroll
                for (int ni = 0; ni < 8; ni++)
                    MMA16816(acc[mi][ni], af[mi], bf[ni]);
        }

        // epilogue from registers: exp(2*sim), mask true diagonal
        const int col0t = colbase + ct * BN;
        const bool diag = (col0t == row0);
#pragma unroll
        for (int mi = 0; mi < 2; mi++) {
#pragma unroll
            for (int ni = 0; ni < 8; ni++) {
                float e0 = fexp2(acc[mi][ni][0] * K2E);
                float e1 = fexp2(acc[mi][ni][1] * K2E);
                float e2 = fexp2(acc[mi][ni][2] * K2E);
                float e3 = fexp2(acc[mi][ni][3] * K2E);
                if (diag) {
                    int gr0 = warp_row + mi * 16 + (lane >> 2);
                    int gc = warp_col + ni * 8 + 2 * (lane & 3);
                    if (gc == gr0) e0 = 0.f;
                    if (gc + 1 == gr0) e1 = 0.f;
                    if (gc == gr0 + 8) e2 = 0.f;
                    if (gc + 1 == gr0 + 8) e3 = 0.f;
                }
                rsum[mi][0] += e0 + e1;
                rsum[mi][1] += e2 + e3;
            }
        }
        __syncthreads();
    }

    // reduce: 4 lanes per row within warp, then 2 col-warps via smem,
    // one atomic per row per CTA.
    float* sred = (float*)smem;   // A tile no longer needed
#pragma unroll
    for (int mi = 0; mi < 2; mi++)
#pragma unroll
        for (int h = 0; h < 2; h++) {
            float v = rsum[mi][h];
            v += __shfl_xor_sync(0xffffffffu, v, 1);
            v += __shfl_xor_sync(0xffffffffu, v, 2);
            if ((lane & 3) == 0 && (wid >> 2) == 1) {
                int lr = warp_row + mi * 16 + h * 8 + (lane >> 2);
                sred[lr] = v;
            }
            rsum[mi][h] = v;
        }
    __syncthreads();
    if ((wid >> 2) == 0 && (lane & 3) == 0) {
#pragma unroll
        for (int mi = 0; mi < 2; mi++)
#pragma unroll
            for (int h = 0; h < 2; h++) {
                int lr = warp_row + mi * 16 + h * 8 + (lane >> 2);
                atomicAdd(&g_denom[row0 + lr], rsum[mi][h] + sred[lr]);
            }
    }
}

// ---------------------------------------------------------------------------
// K3: positive similarities (fp32), one warp per pair.
// ---------------------------------------------------------------------------
__global__ void k_pos() {
    int gw = (blockIdx.x * blockDim.x + threadIdx.x) >> 5;
    int lane = threadIdx.x & 31;
    const float4* a = (const float4*)(g_zn + (size_t)gw * D);
    const float4* b = (const float4*)(g_zn + (size_t)(gw + NHALF) * D);
    float s = 0.f;
#pragma unroll
    for (int p = 0; p < 2; p++) {
        float4 x = a[lane + p * 32];
        float4 y = b[lane + p * 32];
        s += x.x * y.x + x.y * y.y + x.z * y.z + x.w * y.w;
    }
#pragma unroll
    for (int o = 16; o; o >>= 1) s += __shfl_xor_sync(0xffffffffu, s, o);
    if (lane == 0) g_pos[gw] = s;
}

// ---------------------------------------------------------------------------
// K4: weighted loss reduction.
// ---------------------------------------------------------------------------
__global__ void k_loss(const float* __restrict__ w) {
    int i = blockIdx.x * blockDim.x + threadIdx.x;
    float wi = w[i];
    float num = wi * (logf(g_denom[i]) + logf(g_denom[i + NHALF]) - 4.0f * g_pos[i]);
    float den = 2.0f * wi;
#pragma unroll
    for (int o = 16; o; o >>= 1) {
        num += __shfl_xor_sync(0xffffffffu, num, o);
        den += __shfl_xor_sync(0xffffffffu, den, o);
    }
    __shared__ float s_num[8], s_den[8];
    int lane = threadIdx.x & 31, wrp = threadIdx.x >> 5;
    if (lane == 0) { s_num[wrp] = num; s_den[wrp] = den; }
    __syncthreads();
    if (threadIdx.x == 0) {
        float n = 0.f, d = 0.f;
#pragma unroll
        for (int j = 0; j < 8; j++) { n += s_num[j]; d += s_den[j]; }
        atomicAdd(&g_acc[0], n);
        atomicAdd(&g_acc[1], d);
    }
}

__global__ void k_final(float* __restrict__ out) {
    out[0] = g_acc[0] / g_acc[1];
}

// ---------------------------------------------------------------------------
#define SM_TOTAL (3 * 65536)

extern "C" void kernel_launch(void* const* d_in, const int* in_sizes, int n_in,
                              void* d_out, int out_size) {
    const float* z_i = (const float*)d_in[0];
    const float* z_j = (const float*)d_in[1];
    const float* w   = (const float*)d_in[2];
    float* out = (float*)d_out;

    cudaFuncSetAttribute(k_sim, cudaFuncAttributeMaxDynamicSharedMemorySize, SM_TOTAL);

    k_normalize<<<NROWS, 256>>>(z_i, z_j);
    k_sim<<<dim3(NROWS / BM, CSPLIT), 256, SM_TOTAL>>>();
    k_pos<<<NHALF * 32 / 256, 256>>>();
    k_loss<<<NHALF / 256, 256>>>(w);
    k_final<<<1, 1>>>(out);
}

// round 4
// speedup vs baseline: 8.4364x; 1.1074x over previous
#include <cuda_runtime.h>
#include <cuda_bf16.h>
#include <cstdint>
#include <math.h>

#define NHALF 4096
#define NROWS 8192
#define D 256

#define BM 128
#define BN 128
#define CSPLIT 2
#define NT (NROWS / CSPLIT / BN)     // 32 col tiles per CTA

// ---------------- device globals (no allocs allowed) ----------------
__device__ __align__(16) float         g_zn[NROWS * D];    // fp32 rows (pos dot)
__device__ __align__(16) __nv_bfloat16 g_zbf[NROWS * D];   // bf16 rows (MMA)
__device__ float g_denom[NROWS];
__device__ float g_acc[2];

// ---------------- PTX helpers (arch-portable sm_80+ forms only) ----------
__device__ __forceinline__ uint32_t smem_u32(const void* p) {
    uint32_t a;
    asm("{ .reg .u64 t; cvta.to.shared.u64 t, %1; cvt.u32.u64 %0, t; }" : "=r"(a) : "l"(p));
    return a;
}
#define CPASYNC16(dst, src) \
    asm volatile("cp.async.cg.shared.global [%0], [%1], 16;" :: "r"(dst), "l"(src))
#define CPCOMMIT() asm volatile("cp.async.commit_group;" ::: "memory")
#define CPWAIT(n)  asm volatile("cp.async.wait_group %0;" :: "n"(n) : "memory")

#define LDSM4(r0, r1, r2, r3, a) \
    asm volatile("ldmatrix.sync.aligned.m8n8.x4.shared.b16 {%0,%1,%2,%3},[%4];" \
        : "=r"(r0), "=r"(r1), "=r"(r2), "=r"(r3) : "r"(a))

#define MMA16816(d, a, b) \
    asm volatile("mma.sync.aligned.m16n8k16.row.col.f32.bf16.bf16.f32 " \
        "{%0,%1,%2,%3},{%4,%5,%6,%7},{%8,%9},{%0,%1,%2,%3};" \
        : "+f"((d)[0]), "+f"((d)[1]), "+f"((d)[2]), "+f"((d)[3]) \
        : "r"((a)[0]), "r"((a)[1]), "r"((a)[2]), "r"((a)[3]), "r"((b)[0]), "r"((b)[1]))

__device__ __forceinline__ float ex2f(float x) {
    float y;
    asm("ex2.approx.f32 %0, %1;" : "=f"(y) : "f"(x));
    return y;
}

// ---------------------------------------------------------------------------
// K1: normalize rows of concat(z_i,z_j): fp32 + bf16 copies; zero accumulators.
// ---------------------------------------------------------------------------
__global__ void k_normalize(const float* __restrict__ z_i,
                            const float* __restrict__ z_j) {
    int row = blockIdx.x;
    int t = threadIdx.x;
    const float* src = (row < NHALF) ? (z_i + (size_t)row * D)
                                     : (z_j + (size_t)(row - NHALF) * D);
    float v = src[t];
    float ss = v * v;
#pragma unroll
    for (int o = 16; o; o >>= 1) ss += __shfl_xor_sync(0xffffffffu, ss, o);
    __shared__ float sh[8];
    if ((t & 31) == 0) sh[t >> 5] = ss;
    __syncthreads();
    float tot = 0.f;
#pragma unroll
    for (int i = 0; i < 8; i++) tot += sh[i];
    float norm = fmaxf(sqrtf(tot), 1e-8f);
    float zn = v / norm;
    g_zn[(size_t)row * D + t] = zn;
    g_zbf[(size_t)row * D + t] = __float2bfloat16(zn);
    if (t == 0) {
        g_denom[row] = 0.f;
        if (row == 0) { g_acc[0] = 0.f; g_acc[1] = 0.f; }
    }
}

// ---------------------------------------------------------------------------
// Async-copy one 128x256 bf16 tile into XOR-swizzled SMEM.
// SMEM row = 512B = 32 x 16B chunks; chunk cc stored at cc ^ (row & 7).
// ---------------------------------------------------------------------------
__device__ __forceinline__ void load_tile_async(uint32_t sdst, const char* gsrc, int tid) {
#pragma unroll
    for (int i = 0; i < 16; i++) {
        int c = tid + i * 256;            // 0..4095
        int r = c >> 5, cc = c & 31;
        uint32_t dst = sdst + r * 512 + ((cc ^ (r & 7)) << 4);
        CPASYNC16(dst, gsrc + (size_t)c * 16);
    }
}

// ---------------------------------------------------------------------------
// K2: HMMA sim GEMM + MUFU exp + masked row-sum.
// Grid (64, CSPLIT), 256 threads = 8 warps (4 row x 2 col), warp tile 32x64.
// ---------------------------------------------------------------------------
__global__ void __launch_bounds__(256) k_sim() {
    extern __shared__ char smem[];
    const int tid = threadIdx.x;
    const int wid = tid >> 5, lane = tid & 31;
    const int row0 = blockIdx.x * BM;
    const int colbase = blockIdx.y * (NROWS / CSPLIT);
    const int warp_row = (wid & 3) * 32;
    const int warp_col = (wid >> 2) * 64;

    const uint32_t sbA = smem_u32(smem);
    const uint32_t sbB[2] = { sbA + 65536, sbA + 131072 };

    // prologue: A tile + B tile 0 in flight as one group
    load_tile_async(sbA, (const char*)(g_zbf + (size_t)row0 * D), tid);
    load_tile_async(sbB[0], (const char*)(g_zbf + (size_t)colbase * D), tid);
    CPCOMMIT();

    // ldmatrix address precompute
    uint32_t baseA[2]; int swA[2];
    const int hiA = lane >> 4;
#pragma unroll
    for (int mi = 0; mi < 2; mi++) {
        int rA = warp_row + mi * 16 + (lane & 15);
        baseA[mi] = sbA + rA * 512;
        swA[mi] = rA & 7;
    }
    uint32_t relB[4]; int swB[4];
    const int hiB = (lane >> 3) & 1;
#pragma unroll
    for (int np = 0; np < 4; np++) {
        int nB = warp_col + np * 16 + (lane & 7) + ((lane & 16) >> 1);
        relB[np] = nB * 512;
        swB[np] = nB & 7;
    }

    float rsum[2][2] = {{0.f, 0.f}, {0.f, 0.f}};
    const float K2E = 2.8853900817779268f;   // 2 / ln(2): exp(2s) = 2^(s*K2E)

    for (int ct = 0; ct < NT; ct++) {
        const uint32_t sbBt = sbB[ct & 1];
        if (ct + 1 < NT) {
            load_tile_async(sbB[(ct + 1) & 1],
                            (const char*)(g_zbf + (size_t)(colbase + (ct + 1) * BN) * D), tid);
            CPCOMMIT();
            CPWAIT(1);
        } else {
            CPWAIT(0);
        }
        __syncthreads();

        float acc[2][8][4];
#pragma unroll
        for (int mi = 0; mi < 2; mi++)
#pragma unroll
            for (int ni = 0; ni < 8; ni++)
#pragma unroll
                for (int c = 0; c < 4; c++) acc[mi][ni][c] = 0.f;

#pragma unroll
        for (int s = 0; s < 16; s++) {
            uint32_t af[2][4];
#pragma unroll
            for (int mi = 0; mi < 2; mi++)
                LDSM4(af[mi][0], af[mi][1], af[mi][2], af[mi][3],
                      baseA[mi] + (((2 * s + hiA) ^ swA[mi]) << 4));
            uint32_t bf[8][2];
#pragma unroll
            for (int np = 0; np < 4; np++) {
                uint32_t t0, t1, t2, t3;
                LDSM4(t0, t1, t2, t3,
                      sbBt + relB[np] + (((2 * s + hiB) ^ swB[np]) << 4));
                bf[2 * np][0] = t0;     bf[2 * np][1] = t1;
                bf[2 * np + 1][0] = t2; bf[2 * np + 1][1] = t3;
            }
#pragma unroll
            for (int mi = 0; mi < 2; mi++)
#pragma unroll
                for (int ni = 0; ni < 8; ni++)
                    MMA16816(acc[mi][ni], af[mi], bf[ni]);
        }

        // epilogue: exp(2*sim) via MUFU, mask true diagonal (uniform branch)
        const bool diag = (colbase + ct * BN == row0);
#pragma unroll
        for (int mi = 0; mi < 2; mi++) {
#pragma unroll
            for (int ni = 0; ni < 8; ni++) {
                float e0 = ex2f(acc[mi][ni][0] * K2E);
                float e1 = ex2f(acc[mi][ni][1] * K2E);
                float e2 = ex2f(acc[mi][ni][2] * K2E);
                float e3 = ex2f(acc[mi][ni][3] * K2E);
                if (diag) {
                    int gr0 = warp_row + mi * 16 + (lane >> 2);
                    int gc = warp_col + ni * 8 + 2 * (lane & 3);
                    if (gc == gr0) e0 = 0.f;
                    if (gc + 1 == gr0) e1 = 0.f;
                    if (gc == gr0 + 8) e2 = 0.f;
                    if (gc + 1 == gr0 + 8) e3 = 0.f;
                }
                rsum[mi][0] += e0 + e1;
                rsum[mi][1] += e2 + e3;
            }
        }
        __syncthreads();
    }

    // reduce: 4 lanes per row within warp, then 2 col-warps via smem,
    // one atomic per row per CTA.
    float* sred = (float*)smem;   // A tile no longer needed
#pragma unroll
    for (int mi = 0; mi < 2; mi++)
#pragma unroll
        for (int h = 0; h < 2; h++) {
            float v = rsum[mi][h];
            v += __shfl_xor_sync(0xffffffffu, v, 1);
            v += __shfl_xor_sync(0xffffffffu, v, 2);
            if ((lane & 3) == 0 && (wid >> 2) == 1) {
                int lr = warp_row + mi * 16 + h * 8 + (lane >> 2);
                sred[lr] = v;
            }
            rsum[mi][h] = v;
        }
    __syncthreads();
    if ((wid >> 2) == 0 && (lane & 3) == 0) {
#pragma unroll
        for (int mi = 0; mi < 2; mi++)
#pragma unroll
            for (int h = 0; h < 2; h++) {
                int lr = warp_row + mi * 16 + h * 8 + (lane >> 2);
                atomicAdd(&g_denom[row0 + lr], rsum[mi][h] + sred[lr]);
            }
    }
}

// ---------------------------------------------------------------------------
// K3: fused positives + weighted loss. One warp per pair i:
//   pos_i = dot(zn[i], zn[i+N]) in fp32;
//   contribution w_i*(log(den_i) + log(den_{i+N}) - 4*pos_i), weight 2*w_i.
// Block-level reduction, 2 atomics per block.
// ---------------------------------------------------------------------------
__global__ void k_loss(const float* __restrict__ w) {
    int gw = (blockIdx.x * blockDim.x + threadIdx.x) >> 5;   // pair id 0..4095
    int lane = threadIdx.x & 31;
    const float4* a = (const float4*)(g_zn + (size_t)gw * D);
    const float4* b = (const float4*)(g_zn + (size_t)(gw + NHALF) * D);
    float s = 0.f;
#pragma unroll
    for (int p = 0; p < 2; p++) {
        float4 x = a[lane + p * 32];
        float4 y = b[lane + p * 32];
        s += x.x * y.x + x.y * y.y + x.z * y.z + x.w * y.w;
    }
#pragma unroll
    for (int o = 16; o; o >>= 1) s += __shfl_xor_sync(0xffffffffu, s, o);

    __shared__ float s_num[8], s_den[8];
    int wrp = threadIdx.x >> 5;
    if (lane == 0) {
        float wi = w[gw];
        s_num[wrp] = wi * (logf(g_denom[gw]) + logf(g_denom[gw + NHALF]) - 4.0f * s);
        s_den[wrp] = 2.0f * wi;
    }
    __syncthreads();
    if (threadIdx.x == 0) {
        float n = 0.f, d = 0.f;
#pragma unroll
        for (int j = 0; j < 8; j++) { n += s_num[j]; d += s_den[j]; }
        atomicAdd(&g_acc[0], n);
        atomicAdd(&g_acc[1], d);
    }
}

__global__ void k_final(float* __restrict__ out) {
    out[0] = g_acc[0] / g_acc[1];
}

// ---------------------------------------------------------------------------
#define SM_TOTAL (3 * 65536)

extern "C" void kernel_launch(void* const* d_in, const int* in_sizes, int n_in,
                              void* d_out, int out_size) {
    const float* z_i = (const float*)d_in[0];
    const float* z_j = (const float*)d_in[1];
    const float* w   = (const float*)d_in[2];
    float* out = (float*)d_out;

    cudaFuncSetAttribute(k_sim, cudaFuncAttributeMaxDynamicSharedMemorySize, SM_TOTAL);

    k_normalize<<<NROWS, 256>>>(z_i, z_j);
    k_sim<<<dim3(NROWS / BM, CSPLIT), 256, SM_TOTAL>>>();
    k_loss<<<NHALF * 32 / 256, 256>>>(w);
    k_final<<<1, 1>>>(out);
}